// round 1
// baseline (speedup 1.0000x reference)
#include <cuda_runtime.h>
#include <cuda_bf16.h>
#include <math.h>

// Problem constants
#define R_DIM 128
#define C_DIM 256
#define E_DIM 768
#define H_DIM 12
#define DK_DIM 64
#define MROWS (R_DIM * C_DIM)          // 32768
#define PHEAD (R_DIM * DK_DIM)         // 8192  (contraction length per head for scores)
#define SPLIT 8
#define KCHUNK (PHEAD / SPLIT)         // 1024
#define SCORES_ELEMS (H_DIM * C_DIM * C_DIM)  // 786432
#define OUT_ELEMS ((size_t)MROWS * E_DIM)     // 25165824

// ---------------- scratch (device globals: allocation-free rule) ----------------
__device__ float g_qt[(size_t)H_DIM * C_DIM * PHEAD];     // [h][i][r*64+d]
__device__ float g_kt[(size_t)H_DIM * C_DIM * PHEAD];     // [h][j][r*64+d]
__device__ float g_vt[(size_t)H_DIM * R_DIM * C_DIM * DK_DIM]; // [h][r][j][d]
__device__ float g_c [(size_t)MROWS * E_DIM];             // [(r*C+i)][h*64+d]
__device__ float g_part[(size_t)H_DIM * SPLIT * C_DIM * C_DIM]; // split-K partials
__device__ float g_probs[(size_t)SCORES_ELEMS];           // [h][i][j]

// ---------------- generic NT SGEMM: C = A(MxK) * B(NxK)^T ----------------
// BM=BN=128, BK=16, 256 threads, 8x8 per thread.
enum { M_PLAIN = 0, M_Q = 1, M_K = 2, M_V = 3, M_SCORES = 4 };

template<int MODE>
__global__ __launch_bounds__(256)
void sgemm_nt(const float* __restrict__ A, const float* __restrict__ B,
              const float* __restrict__ bias, float* __restrict__ C,
              int M, int N, int K, int lda, int ldb, int ldc, float alpha)
{
    __shared__ float As[16][128];
    __shared__ float Bs[16][128];

    const int t  = threadIdx.x;
    const int tx = t & 15;       // n direction (8 cols each)
    const int ty = t >> 4;       // m direction (8 rows each)
    const int m0 = blockIdx.y * 128;
    const int n0 = blockIdx.x * 128;

    const float* Ab = A;
    const float* Bb = B;
    if (MODE == M_SCORES) {
        const int z = blockIdx.z;
        const int h = z >> 3, s = z & 7;
        Ab = A + (size_t)h * C_DIM * PHEAD + (size_t)s * KCHUNK;
        Bb = B + (size_t)h * C_DIM * PHEAD + (size_t)s * KCHUNK;
        C  = C + (size_t)z * (C_DIM * C_DIM);
    }

    float acc[8][8];
#pragma unroll
    for (int u = 0; u < 8; u++)
#pragma unroll
        for (int v = 0; v < 8; v++) acc[u][v] = 0.0f;

    for (int k0 = 0; k0 < K; k0 += 16) {
#pragma unroll
        for (int it = 0; it < 2; it++) {
            const int f   = t + it * 256;    // 0..511
            const int row = f >> 2;          // 0..127
            const int kq  = f & 3;           // float4 index in k (0..3)
            float4 va = *reinterpret_cast<const float4*>(
                &Ab[(size_t)(m0 + row) * lda + k0 + kq * 4]);
            As[kq * 4 + 0][row] = va.x;
            As[kq * 4 + 1][row] = va.y;
            As[kq * 4 + 2][row] = va.z;
            As[kq * 4 + 3][row] = va.w;
            float4 vb = *reinterpret_cast<const float4*>(
                &Bb[(size_t)(n0 + row) * ldb + k0 + kq * 4]);
            Bs[kq * 4 + 0][row] = vb.x;
            Bs[kq * 4 + 1][row] = vb.y;
            Bs[kq * 4 + 2][row] = vb.z;
            Bs[kq * 4 + 3][row] = vb.w;
        }
        __syncthreads();

#pragma unroll
        for (int kk = 0; kk < 16; kk++) {
            float4 a0 = *reinterpret_cast<const float4*>(&As[kk][ty * 8]);
            float4 a1 = *reinterpret_cast<const float4*>(&As[kk][ty * 8 + 4]);
            float4 b0 = *reinterpret_cast<const float4*>(&Bs[kk][tx * 8]);
            float4 b1 = *reinterpret_cast<const float4*>(&Bs[kk][tx * 8 + 4]);
            float a[8] = {a0.x, a0.y, a0.z, a0.w, a1.x, a1.y, a1.z, a1.w};
            float b[8] = {b0.x, b0.y, b0.z, b0.w, b1.x, b1.y, b1.z, b1.w};
#pragma unroll
            for (int u = 0; u < 8; u++)
#pragma unroll
                for (int v = 0; v < 8; v++)
                    acc[u][v] = fmaf(a[u], b[v], acc[u][v]);
        }
        __syncthreads();
    }

    // epilogue
#pragma unroll
    for (int u = 0; u < 8; u++) {
        const int m = m0 + ty * 8 + u;
#pragma unroll
        for (int v = 0; v < 8; v++) {
            const int n = n0 + tx * 8 + v;
            float val = acc[u][v];
            if (MODE == M_SCORES) {
                C[(size_t)m * C_DIM + n] = val;
            } else if (MODE == M_PLAIN) {
                if (bias) val += bias[n];
                C[(size_t)m * ldc + n] = val;
            } else {
                val += bias[n];
                const int h = n >> 6, d = n & 63;
                const int r = m >> 8, ij = m & 255;   // m = r*C + i
                if (MODE == M_Q) {
                    val *= alpha;
                    C[(((size_t)h * C_DIM + ij) * R_DIM + r) * DK_DIM + d] = val;
                } else if (MODE == M_K) {
                    C[(((size_t)h * C_DIM + ij) * R_DIM + r) * DK_DIM + d] = val;
                } else { // M_V: [h][r][j][d]
                    C[(((size_t)h * R_DIM + r) * C_DIM + ij) * DK_DIM + d] = val;
                }
            }
        }
    }
}

// ---------------- reduce split-K partials + softmax over j ----------------
// one block (256 threads) per (h, i) row
__global__ __launch_bounds__(256)
void softmax_kernel(const float* __restrict__ part, float* __restrict__ probs,
                    float* __restrict__ probs_out)
{
    const int row = blockIdx.x;          // 0 .. H*C-1
    const int h = row >> 8;
    const int i = row & 255;
    const int j = threadIdx.x;

    float v = 0.0f;
#pragma unroll
    for (int s = 0; s < SPLIT; s++)
        v += part[((size_t)(h * SPLIT + s)) * (C_DIM * C_DIM) + (size_t)i * C_DIM + j];

    __shared__ float red[256];
    red[j] = v;
    __syncthreads();
#pragma unroll
    for (int off = 128; off > 0; off >>= 1) {
        if (j < off) red[j] = fmaxf(red[j], red[j + off]);
        __syncthreads();
    }
    const float mx = red[0];
    __syncthreads();

    const float e = expf(v - mx);
    red[j] = e;
    __syncthreads();
#pragma unroll
    for (int off = 128; off > 0; off >>= 1) {
        if (j < off) red[j] += red[j + off];
        __syncthreads();
    }
    const float inv = 1.0f / red[0];

    const float p = e * inv;
    const size_t idx = (size_t)h * C_DIM * C_DIM + (size_t)i * C_DIM + j;
    probs[idx] = p;
    if (probs_out) probs_out[idx] = p;
}

// ---------------- AV: per (h, r): C_hr[i][d] = sum_j P_h[i][j] * V_hr[j][d] ----------------
// grid (C/64, R, H), 256 threads, 64x64 output tile, 4x4 per thread.
__global__ __launch_bounds__(256)
void av_kernel(const float* __restrict__ P, const float* __restrict__ V,
               float* __restrict__ C)
{
    __shared__ float Ps[64][68];   // transposed: [j_local][i_local]
    __shared__ float Vs[64][68];   // [j_local][d]

    const int t  = threadIdx.x;
    const int tx = t & 15;         // d direction (4 each)
    const int ty = t >> 4;         // i direction (4 each)
    const int i0 = blockIdx.x * 64;
    const int r  = blockIdx.y;
    const int h  = blockIdx.z;

    const float* Pb = P + (size_t)h * C_DIM * C_DIM;                  // [i][j]
    const float* Vb = V + ((size_t)h * R_DIM + r) * C_DIM * DK_DIM;   // [j][d]

    float acc[4][4];
#pragma unroll
    for (int u = 0; u < 4; u++)
#pragma unroll
        for (int v = 0; v < 4; v++) acc[u][v] = 0.0f;

    for (int j0 = 0; j0 < C_DIM; j0 += 64) {
#pragma unroll
        for (int it = 0; it < 4; it++) {
            const int f   = t + it * 256;   // 0..1023
            const int row = f >> 4;         // 0..63
            const int c4  = f & 15;         // float4 column index
            float4 pv = *reinterpret_cast<const float4*>(
                &Pb[(size_t)(i0 + row) * C_DIM + j0 + c4 * 4]);
            Ps[c4 * 4 + 0][row] = pv.x;     // transpose into [j][i]
            Ps[c4 * 4 + 1][row] = pv.y;
            Ps[c4 * 4 + 2][row] = pv.z;
            Ps[c4 * 4 + 3][row] = pv.w;
            float4 vv = *reinterpret_cast<const float4*>(
                &Vb[(size_t)(j0 + row) * DK_DIM + c4 * 4]);
            *reinterpret_cast<float4*>(&Vs[row][c4 * 4]) = vv;
        }
        __syncthreads();

#pragma unroll
        for (int kk = 0; kk < 64; kk++) {
            float4 af = *reinterpret_cast<const float4*>(&Ps[kk][ty * 4]);
            float4 bf = *reinterpret_cast<const float4*>(&Vs[kk][tx * 4]);
            float a[4] = {af.x, af.y, af.z, af.w};
            float b[4] = {bf.x, bf.y, bf.z, bf.w};
#pragma unroll
            for (int u = 0; u < 4; u++)
#pragma unroll
                for (int v = 0; v < 4; v++)
                    acc[u][v] = fmaf(a[u], b[v], acc[u][v]);
        }
        __syncthreads();
    }

    // scatter into c[(r*C + i)][h*64 + d]
#pragma unroll
    for (int u = 0; u < 4; u++) {
        const int i = i0 + ty * 4 + u;
        float4 st = make_float4(acc[u][0], acc[u][1], acc[u][2], acc[u][3]);
        *reinterpret_cast<float4*>(
            &C[((size_t)r * C_DIM + i) * E_DIM + h * DK_DIM + tx * 4]) = st;
    }
}

// ---------------- launch ----------------
extern "C" void kernel_launch(void* const* d_in, const int* in_sizes, int n_in,
                              void* d_out, int out_size)
{
    const float* x  = (const float*)d_in[0];
    const float* Wq = (const float*)d_in[1];
    const float* bq = (const float*)d_in[2];
    const float* Wk = (const float*)d_in[3];
    const float* bk = (const float*)d_in[4];
    const float* Wv = (const float*)d_in[5];
    const float* bv = (const float*)d_in[6];
    const float* Wo = (const float*)d_in[7];
    const float* bo = (const float*)d_in[8];
    float* out = (float*)d_out;

    // tuple output: out (25165824 floats) then probs (786432 floats)
    float* probs_out = nullptr;
    if ((size_t)out_size >= OUT_ELEMS + SCORES_ELEMS)
        probs_out = out + ((size_t)out_size - SCORES_ELEMS);

    float *qt, *kt, *vt, *cb, *part, *probs;
    cudaGetSymbolAddress((void**)&qt,    g_qt);
    cudaGetSymbolAddress((void**)&kt,    g_kt);
    cudaGetSymbolAddress((void**)&vt,    g_vt);
    cudaGetSymbolAddress((void**)&cb,    g_c);
    cudaGetSymbolAddress((void**)&part,  g_part);
    cudaGetSymbolAddress((void**)&probs, g_probs);

    const float scaling = (float)(1.0 / (8.0 * sqrt(128.0)));  // dk^-1/2 / sqrt(R)

    dim3 blk(256);
    dim3 gproj(E_DIM / 128, MROWS / 128, 1);   // (6, 256)

    sgemm_nt<M_Q><<<gproj, blk>>>(x, Wq, bq, qt, MROWS, E_DIM, E_DIM,
                                  E_DIM, E_DIM, 0, scaling);
    sgemm_nt<M_K><<<gproj, blk>>>(x, Wk, bk, kt, MROWS, E_DIM, E_DIM,
                                  E_DIM, E_DIM, 0, 1.0f);
    sgemm_nt<M_V><<<gproj, blk>>>(x, Wv, bv, vt, MROWS, E_DIM, E_DIM,
                                  E_DIM, E_DIM, 0, 1.0f);

    dim3 gsc(C_DIM / 128, C_DIM / 128, H_DIM * SPLIT);  // (2, 2, 96)
    sgemm_nt<M_SCORES><<<gsc, blk>>>(qt, kt, nullptr, part, C_DIM, C_DIM, KCHUNK,
                                     PHEAD, PHEAD, C_DIM, 1.0f);

    softmax_kernel<<<H_DIM * C_DIM, 256>>>(part, probs, probs_out);

    dim3 gav(C_DIM / 64, R_DIM, H_DIM);        // (4, 128, 12)
    av_kernel<<<gav, blk>>>(probs, vt, cb);

    sgemm_nt<M_PLAIN><<<gproj, blk>>>(cb, Wo, bo, out, MROWS, E_DIM, E_DIM,
                                      E_DIM, E_DIM, E_DIM, 1.0f);
}

// round 3
// speedup vs baseline: 2.5539x; 2.5539x over previous
#include <cuda_runtime.h>
#include <cuda_bf16.h>
#include <math.h>
#include <stdint.h>

#define R_DIM 128
#define C_DIM 256
#define E_DIM 768
#define H_DIM 12
#define DK_DIM 64
#define MROWS (R_DIM * C_DIM)            // 32768
#define PHEAD (R_DIM * DK_DIM)           // 8192
#define SPLIT_S 4
#define SCORES_ELEMS (H_DIM * C_DIM * C_DIM)   // 786432
#define OUT_ELEMS ((size_t)MROWS * E_DIM)      // 25165824
#define W_ELEMS (E_DIM * E_DIM)                // 589824

typedef unsigned short u16;

// ---------------- scratch (device globals; allocation-free rule) ----------------
__device__ u16 g_xh[OUT_ELEMS],  g_xl[OUT_ELEMS];
__device__ u16 g_wqh[W_ELEMS], g_wql[W_ELEMS];
__device__ u16 g_wkh[W_ELEMS], g_wkl[W_ELEMS];
__device__ u16 g_wvh[W_ELEMS], g_wvl[W_ELEMS];
__device__ u16 g_woh[W_ELEMS], g_wol[W_ELEMS];
__device__ u16 g_qth[OUT_ELEMS], g_qtl[OUT_ELEMS];   // [h][i][r*64+d]
__device__ u16 g_kth[OUT_ELEMS], g_ktl[OUT_ELEMS];   // [h][j][r*64+d]
__device__ u16 g_vth[OUT_ELEMS], g_vtl[OUT_ELEMS];   // [h][r*64+d][j]
__device__ u16 g_pbh[SCORES_ELEMS], g_pbl[SCORES_ELEMS]; // probs bf16 [h][i][j]
__device__ u16 g_cbh[OUT_ELEMS], g_cbl[OUT_ELEMS];   // [(r*C+i)][h*64+d]
__device__ float g_part[(size_t)SPLIT_S * SCORES_ELEMS]; // scores split-K partials
__device__ float g_probs[SCORES_ELEMS];

// ---------------- helpers ----------------
__device__ __forceinline__ uint32_t smem_u32(const void* p) {
    uint32_t a;
    asm("{ .reg .u64 t; cvta.to.shared.u64 t, %1; cvt.u32.u64 %0, t; }" : "=r"(a) : "l"(p));
    return a;
}

// fp32 pair -> (hi pair via truncation, lo pair rounded). low bf16 = x, high = y.
__device__ __forceinline__ void split2(float x, float y, uint32_t& h, uint32_t& l) {
    uint32_t ux = __float_as_uint(x), uy = __float_as_uint(y);
    asm("prmt.b32 %0, %1, %2, 0x7632;" : "=r"(h) : "r"(ux), "r"(uy));
    float hx = __uint_as_float(ux & 0xffff0000u);
    float hy = __uint_as_float(uy & 0xffff0000u);
    asm("cvt.rn.bf16x2.f32 %0, %1, %2;" : "=r"(l) : "f"(y - hy), "f"(x - hx));
}
__device__ __forceinline__ void split1(float x, u16& h, u16& l) {
    uint32_t ux = __float_as_uint(x);
    h = (u16)(ux >> 16);
    float hx = __uint_as_float(ux & 0xffff0000u);
    __nv_bfloat16 lb = __float2bfloat16(x - hx);
    l = *reinterpret_cast<u16*>(&lb);
}

__device__ __forceinline__ void ldm4(uint32_t r[4], uint32_t addr) {
    asm volatile("ldmatrix.sync.aligned.m8n8.x4.shared.b16 {%0,%1,%2,%3}, [%4];"
                 : "=r"(r[0]), "=r"(r[1]), "=r"(r[2]), "=r"(r[3]) : "r"(addr));
}
__device__ __forceinline__ void mma_bf16(float c[4], const uint32_t a[4],
                                         uint32_t b0, uint32_t b1) {
    asm volatile("mma.sync.aligned.m16n8k16.row.col.f32.bf16.bf16.f32 "
        "{%0,%1,%2,%3}, {%4,%5,%6,%7}, {%8,%9}, {%0,%1,%2,%3};"
        : "+f"(c[0]), "+f"(c[1]), "+f"(c[2]), "+f"(c[3])
        : "r"(a[0]), "r"(a[1]), "r"(a[2]), "r"(a[3]), "r"(b0), "r"(b1));
}
#define CP16(dst, src) \
    asm volatile("cp.async.cg.shared.global [%0], [%1], 16;" :: "r"(dst), "l"(src) : "memory")
#define CP_COMMIT() asm volatile("cp.async.commit_group;" ::: "memory")
#define CP_WAIT0()  asm volatile("cp.async.wait_group 0;" ::: "memory")
#define CP_WAIT1()  asm volatile("cp.async.wait_group 1;" ::: "memory")

// ---------------- input convert kernel: fp32 -> bf16 hi/lo ----------------
__global__ __launch_bounds__(256)
void convert_split(const float* __restrict__ src, u16* __restrict__ h,
                   u16* __restrict__ l, int n4)
{
    for (int i = blockIdx.x * blockDim.x + threadIdx.x; i < n4; i += gridDim.x * blockDim.x) {
        float4 v = reinterpret_cast<const float4*>(src)[i];
        uint32_t h01, l01, h23, l23;
        split2(v.x, v.y, h01, l01);
        split2(v.z, v.w, h23, l23);
        reinterpret_cast<uint2*>(h)[i] = make_uint2(h01, h23);
        reinterpret_cast<uint2*>(l)[i] = make_uint2(l01, l23);
    }
}

// ---------------- HMMA GEMM: C = A(MxK) * B(NxK)^T, bf16 hi/lo 3-product ----------------
enum { M_PLAIN = 0, M_QK = 1, M_V = 2, M_SCORES = 3, M_AV = 4 };

#define STAGE_B 40960            // 4 tiles * 128 rows * 40 bf16 * 2B
#define DYN_B   (2 * STAGE_B)    // 81920; epilogue fsm 128*132*4=67584 fits

template<int MODE>
__global__ __launch_bounds__(256, 2)
void hm_gemm(const u16* __restrict__ Ah, const u16* __restrict__ Al,
             const u16* __restrict__ Bh, const u16* __restrict__ Bl,
             const float* __restrict__ bias, float* __restrict__ outF,
             u16* __restrict__ outH, u16* __restrict__ outL,
             int K, int lda, int ldb, float alpha)
{
    extern __shared__ char dynsmem[];
    const int t    = threadIdx.x;
    const int lane = t & 31;
    const int wid  = t >> 5;
    const int wm   = (wid & 3) * 32;
    const int wn   = (wid >> 2) * 64;
    const int m0   = blockIdx.y * 128;
    const int n0   = blockIdx.x * 128;

    int hz = 0;
    if (MODE == M_SCORES) {
        const int z = blockIdx.z;
        const int h = z >> 2, s = z & 3;
        const size_t off = (size_t)h * C_DIM * PHEAD + (size_t)s * (PHEAD / SPLIT_S);
        Ah += off; Al += off; Bh += off; Bl += off;
        outF += (size_t)z * (C_DIM * C_DIM);
    } else if (MODE == M_AV) {
        hz = blockIdx.z;
        const size_t ao = (size_t)hz * C_DIM * C_DIM;
        const size_t bo = (size_t)hz * PHEAD * C_DIM;
        Ah += ao; Al += ao; Bh += bo; Bl += bo;
    }

    const uint32_t smb = smem_u32(dynsmem);
    const int NC = K >> 5;

    // -------- cp.async issue of one 32-K chunk into stage s --------
    auto issue = [&](int c, int s) {
        const int kk = c << 5;
        const uint32_t sb = smb + s * STAGE_B;
#pragma unroll
        for (int it = 0; it < 2; it++) {
            const int f = t + it * 256;        // 0..511
            const int row = f >> 2;            // 0..127
            const int k8  = f & 3;
            const uint32_t so = (uint32_t)(row * 80 + k8 * 16);
            const size_t ga = (size_t)(m0 + row) * lda + kk + k8 * 8;
            const size_t gb = (size_t)(n0 + row) * ldb + kk + k8 * 8;
            CP16(sb +     0 + so, Ah + ga);
            CP16(sb + 10240 + so, Al + ga);
            CP16(sb + 20480 + so, Bh + gb);
            CP16(sb + 30720 + so, Bl + gb);
        }
        CP_COMMIT();
    };

    float acc[2][8][4];
#pragma unroll
    for (int mt = 0; mt < 2; mt++)
#pragma unroll
        for (int nt = 0; nt < 8; nt++)
#pragma unroll
            for (int e = 0; e < 4; e++) acc[mt][nt][e] = 0.0f;

    // per-thread ldmatrix lane offsets
    const uint32_t ro = (uint32_t)(((lane >> 3) & 1) * 8 + (lane & 7));
    const uint32_t co = (lane & 16) ? 16u : 0u;     // bytes
    const uint32_t aoff = (uint32_t)(wm + ro) * 80 + co;
    const uint32_t boff = (uint32_t)(wn + ro) * 80 + co;

    issue(0, 0);
    if (NC > 1) issue(1, 1);

    for (int c = 0; c < NC; c++) {
        if (c == NC - 1) { CP_WAIT0(); } else { CP_WAIT1(); }
        __syncthreads();

        const uint32_t sb = smb + (c & 1) * STAGE_B;
#pragma unroll
        for (int kh = 0; kh < 2; kh++) {
            const uint32_t kB = kh * 32;   // 16 bf16 * 2B
            uint32_t aH[2][4], aL[2][4], bH[4][4];
            ldm4(aH[0], sb + aoff + kB);
            ldm4(aH[1], sb + aoff + 16 * 80 + kB);
#pragma unroll
            for (int np = 0; np < 4; np++)
                ldm4(bH[np], sb + 20480 + boff + np * 16 * 80 + kB);
            // pass 1: Ah * Bh
#pragma unroll
            for (int mt = 0; mt < 2; mt++)
#pragma unroll
                for (int np = 0; np < 4; np++) {
                    mma_bf16(acc[mt][np * 2 + 0], aH[mt], bH[np][0], bH[np][2]);
                    mma_bf16(acc[mt][np * 2 + 1], aH[mt], bH[np][1], bH[np][3]);
                }
            // pass 2: Al * Bh
            ldm4(aL[0], sb + 10240 + aoff + kB);
            ldm4(aL[1], sb + 10240 + aoff + 16 * 80 + kB);
#pragma unroll
            for (int mt = 0; mt < 2; mt++)
#pragma unroll
                for (int np = 0; np < 4; np++) {
                    mma_bf16(acc[mt][np * 2 + 0], aL[mt], bH[np][0], bH[np][2]);
                    mma_bf16(acc[mt][np * 2 + 1], aL[mt], bH[np][1], bH[np][3]);
                }
            // pass 3: Ah * Bl (reload per np to cap registers)
#pragma unroll
            for (int np = 0; np < 4; np++) {
                uint32_t bL[4];
                ldm4(bL, sb + 30720 + boff + np * 16 * 80 + kB);
                mma_bf16(acc[0][np * 2 + 0], aH[0], bL[0], bL[2]);
                mma_bf16(acc[0][np * 2 + 1], aH[0], bL[1], bL[3]);
                mma_bf16(acc[1][np * 2 + 0], aH[1], bL[0], bL[2]);
                mma_bf16(acc[1][np * 2 + 1], aH[1], bL[1], bL[3]);
            }
        }
        __syncthreads();
        if (c + 2 < NC) issue(c + 2, c & 1);
    }

    // -------- epilogue: acc -> smem fp32 staging -> global --------
    float* fsm = reinterpret_cast<float*>(dynsmem);
    {
        const int g  = lane >> 2;
        const int tg = lane & 3;
#pragma unroll
        for (int mt = 0; mt < 2; mt++)
#pragma unroll
            for (int nt = 0; nt < 8; nt++) {
                const int r0 = wm + mt * 16 + g;
                const int cc = wn + nt * 8 + 2 * tg;
                *reinterpret_cast<float2*>(&fsm[r0 * 132 + cc]) =
                    make_float2(acc[mt][nt][0], acc[mt][nt][1]);
                *reinterpret_cast<float2*>(&fsm[(r0 + 8) * 132 + cc]) =
                    make_float2(acc[mt][nt][2], acc[mt][nt][3]);
            }
    }
    __syncthreads();

    if (MODE == M_V) {
        // transposed scatter: vt[h][r*64+d][j] (+ bias), coalesced along j
#pragma unroll 8
        for (int i = 0; i < 64; i++) {
            const int f = t + i * 256;      // 0..16383
            const int m = f & 127;          // tile row  -> (r, j)
            const int n = f >> 7;           // tile col  -> (h, d)
            const int ng = n0 + n;
            float v = fsm[m * 132 + n] + bias[ng];
            const int h = ng >> 6, d = ng & 63;
            const int mg = m0 + m;
            const int r = mg >> 8, j = mg & 255;
            u16 hh, ll;
            split1(v, hh, ll);
            const size_t oi = ((size_t)h * PHEAD + r * 64 + d) * C_DIM + j;
            outH[oi] = hh; outL[oi] = ll;
        }
    } else {
#pragma unroll
        for (int i = 0; i < 16; i++) {
            const int f = t + i * 256;
            const int row = f >> 5;
            const int q   = f & 31;
            float4 v = *reinterpret_cast<const float4*>(&fsm[row * 132 + q * 4]);
            const int m = m0 + row;
            const int n = n0 + q * 4;
            if (MODE == M_SCORES) {
                *reinterpret_cast<float4*>(&outF[(size_t)m * C_DIM + n]) = v;
            } else if (MODE == M_PLAIN) {
                float4 bb = *reinterpret_cast<const float4*>(&bias[n]);
                v.x += bb.x; v.y += bb.y; v.z += bb.z; v.w += bb.w;
                *reinterpret_cast<float4*>(&outF[(size_t)m * E_DIM + n]) = v;
            } else if (MODE == M_QK) {
                float4 bb = *reinterpret_cast<const float4*>(&bias[n]);
                v.x = (v.x + bb.x) * alpha; v.y = (v.y + bb.y) * alpha;
                v.z = (v.z + bb.z) * alpha; v.w = (v.w + bb.w) * alpha;
                uint32_t h01, l01, h23, l23;
                split2(v.x, v.y, h01, l01);
                split2(v.z, v.w, h23, l23);
                const int h = n >> 6, d = n & 63;
                const int r = m >> 8, ij = m & 255;
                const size_t oi = ((size_t)h * C_DIM + ij) * PHEAD + r * 64 + d;
                *reinterpret_cast<uint2*>(&outH[oi]) = make_uint2(h01, h23);
                *reinterpret_cast<uint2*>(&outL[oi]) = make_uint2(l01, l23);
            } else { // M_AV -> cb[(r*C+i)][hz*64+d]
                uint32_t h01, l01, h23, l23;
                split2(v.x, v.y, h01, l01);
                split2(v.z, v.w, h23, l23);
                const int r = n >> 6, d = n & 63;
                const size_t oi = ((size_t)r * C_DIM + m) * E_DIM + hz * 64 + d;
                *reinterpret_cast<uint2*>(&outH[oi]) = make_uint2(h01, h23);
                *reinterpret_cast<uint2*>(&outL[oi]) = make_uint2(l01, l23);
            }
        }
    }
}

// ---------------- softmax: reduce split-K partials, softmax, emit fp32 + bf16 ----------------
__global__ __launch_bounds__(256)
void softmax_kernel(const float* __restrict__ part, float* __restrict__ probs,
                    float* __restrict__ probs_out,
                    u16* __restrict__ pbh, u16* __restrict__ pbl)
{
    const int row = blockIdx.x;          // h*256 + i
    const int h = row >> 8;
    const int i = row & 255;
    const int j = threadIdx.x;

    float v = 0.0f;
#pragma unroll
    for (int s = 0; s < SPLIT_S; s++)
        v += part[((size_t)(h * SPLIT_S + s)) * (C_DIM * C_DIM) + (size_t)i * C_DIM + j];

    __shared__ float red[256];
    red[j] = v;
    __syncthreads();
#pragma unroll
    for (int off = 128; off > 0; off >>= 1) {
        if (j < off) red[j] = fmaxf(red[j], red[j + off]);
        __syncthreads();
    }
    const float mx = red[0];
    __syncthreads();
    const float e = expf(v - mx);
    red[j] = e;
    __syncthreads();
#pragma unroll
    for (int off = 128; off > 0; off >>= 1) {
        if (j < off) red[j] += red[j + off];
        __syncthreads();
    }
    const float p = e / red[0];

    const size_t idx = (size_t)row * C_DIM + j;
    probs[idx] = p;
    if (probs_out) probs_out[idx] = p;
    u16 hh, ll;
    split1(p, hh, ll);
    pbh[idx] = hh; pbl[idx] = ll;
}

// ---------------- launch ----------------
extern "C" void kernel_launch(void* const* d_in, const int* in_sizes, int n_in,
                              void* d_out, int out_size)
{
    const float* x  = (const float*)d_in[0];
    const float* Wq = (const float*)d_in[1];
    const float* bq = (const float*)d_in[2];
    const float* Wk = (const float*)d_in[3];
    const float* bk = (const float*)d_in[4];
    const float* Wv = (const float*)d_in[5];
    const float* bv = (const float*)d_in[6];
    const float* Wo = (const float*)d_in[7];
    const float* bo = (const float*)d_in[8];
    float* out = (float*)d_out;

    float* probs_out = nullptr;
    if ((size_t)out_size >= OUT_ELEMS + SCORES_ELEMS)
        probs_out = out + ((size_t)out_size - SCORES_ELEMS);

    u16 *xh, *xl, *wqh, *wql, *wkh, *wkl, *wvh, *wvl, *woh, *wol;
    u16 *qth, *qtl, *kth, *ktl, *vth, *vtl, *pbh, *pbl, *cbh, *cbl;
    float *part, *probs;
    cudaGetSymbolAddress((void**)&xh, g_xh);   cudaGetSymbolAddress((void**)&xl, g_xl);
    cudaGetSymbolAddress((void**)&wqh, g_wqh); cudaGetSymbolAddress((void**)&wql, g_wql);
    cudaGetSymbolAddress((void**)&wkh, g_wkh); cudaGetSymbolAddress((void**)&wkl, g_wkl);
    cudaGetSymbolAddress((void**)&wvh, g_wvh); cudaGetSymbolAddress((void**)&wvl, g_wvl);
    cudaGetSymbolAddress((void**)&woh, g_woh); cudaGetSymbolAddress((void**)&wol, g_wol);
    cudaGetSymbolAddress((void**)&qth, g_qth); cudaGetSymbolAddress((void**)&qtl, g_qtl);
    cudaGetSymbolAddress((void**)&kth, g_kth); cudaGetSymbolAddress((void**)&ktl, g_ktl);
    cudaGetSymbolAddress((void**)&vth, g_vth); cudaGetSymbolAddress((void**)&vtl, g_vtl);
    cudaGetSymbolAddress((void**)&pbh, g_pbh); cudaGetSymbolAddress((void**)&pbl, g_pbl);
    cudaGetSymbolAddress((void**)&cbh, g_cbh); cudaGetSymbolAddress((void**)&cbl, g_cbl);
    cudaGetSymbolAddress((void**)&part, g_part);
    cudaGetSymbolAddress((void**)&probs, g_probs);

    cudaFuncSetAttribute(hm_gemm<M_PLAIN>,  cudaFuncAttributeMaxDynamicSharedMemorySize, DYN_B);
    cudaFuncSetAttribute(hm_gemm<M_QK>,     cudaFuncAttributeMaxDynamicSharedMemorySize, DYN_B);
    cudaFuncSetAttribute(hm_gemm<M_V>,      cudaFuncAttributeMaxDynamicSharedMemorySize, DYN_B);
    cudaFuncSetAttribute(hm_gemm<M_SCORES>, cudaFuncAttributeMaxDynamicSharedMemorySize, DYN_B);
    cudaFuncSetAttribute(hm_gemm<M_AV>,     cudaFuncAttributeMaxDynamicSharedMemorySize, DYN_B);

    const float scaling = (float)(1.0 / (8.0 * sqrt(128.0)));

    // input conversions
    convert_split<<<1024, 256>>>(x,  xh,  xl,  OUT_ELEMS / 4);
    convert_split<<<288,  256>>>(Wq, wqh, wql, W_ELEMS / 4);
    convert_split<<<288,  256>>>(Wk, wkh, wkl, W_ELEMS / 4);
    convert_split<<<288,  256>>>(Wv, wvh, wvl, W_ELEMS / 4);
    convert_split<<<288,  256>>>(Wo, wol ? woh : woh, wol, W_ELEMS / 4);

    dim3 blk(256);
    dim3 gproj(E_DIM / 128, MROWS / 128, 1);            // (6, 256)

    hm_gemm<M_QK><<<gproj, blk, DYN_B>>>(xh, xl, wqh, wql, bq, nullptr, qth, qtl,
                                         E_DIM, E_DIM, E_DIM, scaling);
    hm_gemm<M_QK><<<gproj, blk, DYN_B>>>(xh, xl, wkh, wkl, bk, nullptr, kth, ktl,
                                         E_DIM, E_DIM, E_DIM, 1.0f);
    hm_gemm<M_V><<<gproj, blk, DYN_B>>>(xh, xl, wvh, wvl, bv, nullptr, vth, vtl,
                                        E_DIM, E_DIM, E_DIM, 1.0f);

    dim3 gsc(C_DIM / 128, C_DIM / 128, H_DIM * SPLIT_S); // (2, 2, 48)
    hm_gemm<M_SCORES><<<gsc, blk, DYN_B>>>(qth, qtl, kth, ktl, nullptr, part,
                                           nullptr, nullptr,
                                           PHEAD / SPLIT_S, PHEAD, PHEAD, 1.0f);

    softmax_kernel<<<H_DIM * C_DIM, 256>>>(part, probs, probs_out, pbh, pbl);

    dim3 gav(PHEAD / 128, C_DIM / 128, H_DIM);           // (64, 2, 12)
    hm_gemm<M_AV><<<gav, blk, DYN_B>>>(pbh, pbl, vth, vtl, nullptr, nullptr,
                                       cbh, cbl, C_DIM, C_DIM, C_DIM, 1.0f);

    hm_gemm<M_PLAIN><<<gproj, blk, DYN_B>>>(cbh, cbl, woh, wol, bo, out,
                                            nullptr, nullptr, E_DIM, E_DIM, E_DIM, 1.0f);
}